// round 9
// baseline (speedup 1.0000x reference)
#include <cuda_runtime.h>
#include <cstdint>

// Problem shape (fixed by reference)
#define T_DIM 16384
#define B_DIM 64
#define E_DIM 4096

// Permuted scratch layout so the single-block scan kernel is fully coalesced:
//   P(t) = (t & 15) * 1024 + (t >> 4)
// Scan thread `tid` owns t = 16*tid + i (i=0..15) -> permuted addr i*1024+tid
// -> every warp access is one coalesced transaction.
__device__ __forceinline__ int PERM(int t) { return ((t & 15) << 10) | (t >> 4); }

// Scratch (allocation-free). Packed float2: (.x=alpha/A, .y=beta/B)
__device__ float2 g_ab[T_DIM];
__device__ float2 g_AB[T_DIM];

// ---------------------------------------------------------------------------
// Kernel 1: per-t gather + reduce over B=64.
// At the L1tex within-LDG replay floor (~1M random 32B-sector wavefronts at
// ~2 cyc/wf): ~9.6us, occupancy-invariant (verified R6/R7/R8). Keep as is.
// ---------------------------------------------------------------------------
#define K1_ROWS 2
__global__ void __launch_bounds__(512) gather_reduce_kernel(
        const int* __restrict__ indices, const float* __restrict__ params) {
    int gwarp = (blockIdx.x * blockDim.x + threadIdx.x) >> 5;
    int lane  = threadIdx.x & 31;
    int t0 = gwarp * K1_ROWS;

    const float2* p2 = (const float2*)params;

    int2 idx[K1_ROWS];
    #pragma unroll
    for (int r = 0; r < K1_ROWS; r++) {
        idx[r] = ((const int2*)(indices + (size_t)(t0 + r) * B_DIM))[lane];
    }

    float2 v0[K1_ROWS], v1[K1_ROWS];
    #pragma unroll
    for (int r = 0; r < K1_ROWS; r++) v0[r] = __ldg(&p2[idx[r].x]);
    #pragma unroll
    for (int r = 0; r < K1_ROWS; r++) v1[r] = __ldg(&p2[idx[r].y]);

    #pragma unroll
    for (int r = 0; r < K1_ROWS; r++) {
        float sa = v0[r].x + v1[r].x;
        float sb = v0[r].y + v1[r].y;
        #pragma unroll
        for (int off = 16; off > 0; off >>= 1) {
            sa += __shfl_xor_sync(0xFFFFFFFFu, sa, off);
            sb += __shfl_xor_sync(0xFFFFFFFFu, sb, off);
        }
        if (lane == 0) {
            g_ab[PERM(t0 + r)] = make_float2(sa, sb);
        }
    }
}

// ---------------------------------------------------------------------------
// Kernel 2: linear-recurrence scan over T=16384.
// Single block, 1024 threads, 16 elements/thread, shuffle-based block scan.
// Compose (ordered): compose(earlier=(A,B), later=(a,b)) = (a*A, a*B + b)
// ---------------------------------------------------------------------------
__global__ void __launch_bounds__(1024) scan_kernel() {
    __shared__ float2 sW[32];   // per-warp inclusive totals

    const int tid  = threadIdx.x;
    const int lane = tid & 31;
    const int wid  = tid >> 5;

    float2 e[16];
    #pragma unroll
    for (int i = 0; i < 16; i++) e[i] = g_ab[i * 1024 + tid];

    // thread-local inclusive aggregate (in order)
    float ca = 1.0f, cb = 0.0f;
    #pragma unroll
    for (int i = 0; i < 16; i++) {
        cb = fmaf(e[i].x, cb, e[i].y);
        ca = e[i].x * ca;
    }

    // warp inclusive scan over thread aggregates:
    // new = compose(prev_from_lower=(pa,pb), mine=(wa,wb)) = (wa*pa, wa*pb+wb)
    float wa = ca, wb = cb;
    #pragma unroll
    for (int off = 1; off < 32; off <<= 1) {
        float pa = __shfl_up_sync(0xFFFFFFFFu, wa, off);
        float pb = __shfl_up_sync(0xFFFFFFFFu, wb, off);
        float na = (lane >= off) ? wa * pa : wa;
        float nb = (lane >= off) ? fmaf(wa, pb, wb) : wb;
        wa = na; wb = nb;
    }

    if (lane == 31) sW[wid] = make_float2(wa, wb);
    __syncthreads();

    // warp 0 scans the 32 warp totals (inclusive)
    if (wid == 0) {
        float xa = sW[lane].x, xb = sW[lane].y;
        #pragma unroll
        for (int off = 1; off < 32; off <<= 1) {
            float pa = __shfl_up_sync(0xFFFFFFFFu, xa, off);
            float pb = __shfl_up_sync(0xFFFFFFFFu, xb, off);
            float na = (lane >= off) ? xa * pa : xa;
            float nb = (lane >= off) ? fmaf(xa, pb, xb) : xb;
            xa = na; xb = nb;
        }
        sW[lane] = make_float2(xa, xb);
    }
    __syncthreads();

    // block-exclusive prefix = compose(warp_prefix, lane_exclusive)
    float wpa = (wid > 0) ? sW[wid - 1].x : 1.0f;
    float wpb = (wid > 0) ? sW[wid - 1].y : 0.0f;
    float lea = __shfl_up_sync(0xFFFFFFFFu, wa, 1);
    float leb = __shfl_up_sync(0xFFFFFFFFu, wb, 1);
    if (lane == 0) { lea = 1.0f; leb = 0.0f; }
    float pa = lea * wpa;
    float pb = fmaf(lea, wpb, leb);

    // replay local elements applying prefix; coalesced permuted writes
    #pragma unroll
    for (int i = 0; i < 16; i++) {
        pb = fmaf(e[i].x, pb, e[i].y);
        pa = e[i].x * pa;
        g_AB[i * 1024 + tid] = make_float2(pa, pb);
    }
}

// ---------------------------------------------------------------------------
// Kernel 3: output broadcast.  out[t, e] = A[t] * M_prev[e] + B[t]
// One block (1024 threads) owns 16 FULL rows = 256 KB fully contiguous in
// the output -> linear write stream per block, maximal DRAM row-buffer hits.
// Thread tid holds M_prev[4*tid..4*tid+3] in a register float4; 16
// independent STG.128 (__stcs: write-once output, 2x L2 capacity).
// ---------------------------------------------------------------------------
#define K3_ROWS 16
__global__ void __launch_bounds__(1024) broadcast_kernel(
        const float* __restrict__ M_prev, float* __restrict__ out) {
    __shared__ float2 sAB[K3_ROWS];

    const int t0  = blockIdx.x * K3_ROWS;   // multiple of 16
    const int grp = t0 >> 4;                // PERM(t0+r) = r*1024 + grp
    if (threadIdx.x < K3_ROWS) {
        sAB[threadIdx.x] = g_AB[threadIdx.x * 1024 + grp];
    }

    float4 m = __ldg(&((const float4*)M_prev)[threadIdx.x]);  // E/4 == 1024
    __syncthreads();

    float4* o4 = (float4*)out + (size_t)t0 * (E_DIM / 4) + threadIdx.x;
    #pragma unroll
    for (int r = 0; r < K3_ROWS; r++) {
        float a = sAB[r].x;
        float b = sAB[r].y;
        float4 v;
        v.x = fmaf(a, m.x, b);
        v.y = fmaf(a, m.y, b);
        v.z = fmaf(a, m.z, b);
        v.w = fmaf(a, m.w, b);
        __stcs(o4 + (size_t)r * (E_DIM / 4), v);
    }
}

// ---------------------------------------------------------------------------
extern "C" void kernel_launch(void* const* d_in, const int* in_sizes, int n_in,
                              void* d_out, int out_size) {
    const int*   indices = (const int*)d_in[0];   // (T, B) int32 (JAX downcast)
    const float* M_prev  = (const float*)d_in[1]; // (E,)   f32
    const float* params  = (const float*)d_in[2]; // (N, 2) f32
    float*       out     = (float*)d_out;         // (T, E) f32

    // K1: 8192 warps (2 rows each), 512-thread blocks
    gather_reduce_kernel<<<T_DIM / K1_ROWS * 32 / 512, 512>>>(indices, params);

    // K2: single-block shuffle scan
    scan_kernel<<<1, 1024>>>();

    // K3: 1024 blocks x 1024 threads, 16 contiguous rows per block
    broadcast_kernel<<<T_DIM / K3_ROWS, 1024>>>(M_prev, out);
}